// round 1
// baseline (speedup 1.0000x reference)
#include <cuda_runtime.h>
#include <math.h>

// Problem dims (fixed by the reference)
#define TT 4096
#define CC 1024
#define HF 4096
#define NH 16
#define HD 64

// ---------------- scratch (device globals: allocation-free) ----------------
__device__ float g_xn [(size_t)TT * CC];        // rmsnorm output (reused for both norms)
__device__ float g_qkv[(size_t)TT * 3 * CC];    // qkv projection
__device__ float g_y  [(size_t)TT * CC];        // attention output (pre-proj)
__device__ float g_x1 [(size_t)TT * CC];        // residual after attention
__device__ float g_h1 [(size_t)TT * HF];        // ffn gate (silu path), becomes h in-place
__device__ float g_h3 [(size_t)TT * HF];        // ffn up path

// ---------------- RMSNorm: one block per row ----------------
__global__ void rmsnorm_kernel(const float* __restrict__ x,
                               const float* __restrict__ w,
                               float* __restrict__ o, int C) {
    int row = blockIdx.x;
    const float* xr = x + (size_t)row * C;
    float s = 0.f;
    for (int i = threadIdx.x; i < C; i += blockDim.x) {
        float v = xr[i];
        s += v * v;
    }
    __shared__ float red[32];
    #pragma unroll
    for (int off = 16; off; off >>= 1) s += __shfl_down_sync(0xFFFFFFFFu, s, off);
    if ((threadIdx.x & 31) == 0) red[threadIdx.x >> 5] = s;
    __syncthreads();
    if (threadIdx.x < 32) {
        float v = (threadIdx.x < (blockDim.x >> 5)) ? red[threadIdx.x] : 0.f;
        #pragma unroll
        for (int off = 16; off; off >>= 1) v += __shfl_down_sync(0xFFFFFFFFu, v, off);
        if (threadIdx.x == 0) red[0] = v;
    }
    __syncthreads();
    float inv = rsqrtf(red[0] / (float)C + 1e-6f);
    for (int i = threadIdx.x; i < C; i += blockDim.x)
        o[(size_t)row * C + i] = xr[i] * inv * w[i];
}

// ---------------- SGEMM: C[M,N] = A[M,K] * B[N,K]^T (+ add[M,N]) ----------------
// Classic 128x128x8 tile, 256 threads, 8x8 register micro-tile.
#define BM 128
#define BN 128
#define BK 8

__global__ void __launch_bounds__(256)
sgemm_nt(const float* __restrict__ A, const float* __restrict__ B,
         float* __restrict__ C, int M, int N, int K,
         const float* __restrict__ add) {
    __shared__ float As[BK][BM + 4];
    __shared__ float Bs[BK][BN + 4];

    const int bm = blockIdx.y * BM;
    const int bn = blockIdx.x * BN;
    const int tid = threadIdx.x;
    const int tx = tid & 15;       // 0..15 -> cols
    const int ty = tid >> 4;       // 0..15 -> rows

    // load mapping: each thread loads one float4 of A and one of B per k-tile
    const int lr = tid >> 1;            // 0..127 (row in tile)
    const int lc = (tid & 1) * 4;       // 0 or 4 (k offset)

    float acc[8][8];
    #pragma unroll
    for (int i = 0; i < 8; i++)
        #pragma unroll
        for (int j = 0; j < 8; j++) acc[i][j] = 0.f;

    for (int k0 = 0; k0 < K; k0 += BK) {
        float4 av = *(const float4*)(A + (size_t)(bm + lr) * K + k0 + lc);
        float4 bv = *(const float4*)(B + (size_t)(bn + lr) * K + k0 + lc);
        As[lc + 0][lr] = av.x; As[lc + 1][lr] = av.y;
        As[lc + 2][lr] = av.z; As[lc + 3][lr] = av.w;
        Bs[lc + 0][lr] = bv.x; Bs[lc + 1][lr] = bv.y;
        Bs[lc + 2][lr] = bv.z; Bs[lc + 3][lr] = bv.w;
        __syncthreads();

        #pragma unroll
        for (int k = 0; k < BK; k++) {
            float a[8], b[8];
            *(float4*)(a)     = *(const float4*)&As[k][ty * 8];
            *(float4*)(a + 4) = *(const float4*)&As[k][ty * 8 + 4];
            *(float4*)(b)     = *(const float4*)&Bs[k][tx * 8];
            *(float4*)(b + 4) = *(const float4*)&Bs[k][tx * 8 + 4];
            #pragma unroll
            for (int i = 0; i < 8; i++)
                #pragma unroll
                for (int j = 0; j < 8; j++)
                    acc[i][j] = fmaf(a[i], b[j], acc[i][j]);
        }
        __syncthreads();
    }

    #pragma unroll
    for (int i = 0; i < 8; i++) {
        size_t r = (size_t)(bm + ty * 8 + i);
        float* crow = C + r * N + bn + tx * 8;
        float4 v0 = make_float4(acc[i][0], acc[i][1], acc[i][2], acc[i][3]);
        float4 v1 = make_float4(acc[i][4], acc[i][5], acc[i][6], acc[i][7]);
        if (add) {
            const float* arow = add + r * N + bn + tx * 8;
            float4 a0 = *(const float4*)(arow);
            float4 a1 = *(const float4*)(arow + 4);
            v0.x += a0.x; v0.y += a0.y; v0.z += a0.z; v0.w += a0.w;
            v1.x += a1.x; v1.y += a1.y; v1.z += a1.z; v1.w += a1.w;
        }
        *(float4*)(crow)     = v0;
        *(float4*)(crow + 4) = v1;
    }
}

// ---------------- Flash attention (causal), fp32 ----------------
// Block = (query tile of 64 rows) x (one head). 256 threads = 16x16.
// Thread (ty,tx) owns rows {ty+16i} and cols {tx+16j}, i,j in 0..3.
// Smem pad 65 makes transpose scatter-stores conflict-free (65 ≡ 1 mod 32);
// all inner-loop loads are broadcast or stride-1.
__global__ void __launch_bounds__(256)
attn_kernel(const float* __restrict__ qkv, float* __restrict__ y) {
    extern __shared__ float sm[];
    float (*Qt)[65] = (float(*)[65])(sm);                 // [k][r]
    float (*Kt)[65] = (float(*)[65])(sm + 64 * 65);       // [k][c]
    float (*Ps)[65] = (float(*)[65])(sm + 2 * 64 * 65);   // [r][j]
    float (*Vs)[64] = (float(*)[64])(sm + 3 * 64 * 65);   // [j][d]

    const int qt = blockIdx.x;       // query tile
    const int h  = blockIdx.y;       // head
    const int tid = threadIdx.x;
    const int tx = tid & 15;
    const int ty = tid >> 4;
    const int C3 = 3 * CC;
    const int q0 = qt * 64;
    const float scale = 0.125f;      // 1/sqrt(64)

    // Load Q tile transposed: Qt[d][r]
    for (int f = tid; f < 64 * 64; f += 256) {
        int r = f >> 6, d = f & 63;
        Qt[d][r] = qkv[(size_t)(q0 + r) * C3 + h * HD + d];
    }

    float m[4], l[4], O[4][4];
    #pragma unroll
    for (int i = 0; i < 4; i++) {
        m[i] = -1e30f; l[i] = 0.f;
        #pragma unroll
        for (int j = 0; j < 4; j++) O[i][j] = 0.f;
    }
    __syncthreads();

    for (int kt = 0; kt <= qt; kt++) {
        const int k0 = kt * 64;
        // Load K transposed + V natural
        for (int f = tid; f < 64 * 64; f += 256) {
            int r = f >> 6, d = f & 63;
            Kt[d][r] = qkv[(size_t)(k0 + r) * C3 + CC     + h * HD + d];
            Vs[r][d] = qkv[(size_t)(k0 + r) * C3 + 2 * CC + h * HD + d];
        }
        __syncthreads();

        // S = Q K^T (64x64 tile)
        float S[4][4];
        #pragma unroll
        for (int i = 0; i < 4; i++)
            #pragma unroll
            for (int j = 0; j < 4; j++) S[i][j] = 0.f;

        #pragma unroll 8
        for (int k = 0; k < HD; k++) {
            float q[4], kk[4];
            #pragma unroll
            for (int i = 0; i < 4; i++) {
                q[i]  = Qt[k][ty + 16 * i];
                kk[i] = Kt[k][tx + 16 * i];
            }
            #pragma unroll
            for (int i = 0; i < 4; i++)
                #pragma unroll
                for (int j = 0; j < 4; j++)
                    S[i][j] = fmaf(q[i], kk[j], S[i][j]);
        }

        // scale + causal mask on diagonal tile
        if (kt == qt) {
            #pragma unroll
            for (int i = 0; i < 4; i++)
                #pragma unroll
                for (int j = 0; j < 4; j++) {
                    int rr = ty + 16 * i, cc = tx + 16 * j;
                    S[i][j] = (cc <= rr) ? S[i][j] * scale : -1e30f;
                }
        } else {
            #pragma unroll
            for (int i = 0; i < 4; i++)
                #pragma unroll
                for (int j = 0; j < 4; j++) S[i][j] *= scale;
        }

        // Online softmax per row (reduce over 16 tx lanes, same half-warp)
        #pragma unroll
        for (int i = 0; i < 4; i++) {
            float mx = S[i][0];
            #pragma unroll
            for (int j = 1; j < 4; j++) mx = fmaxf(mx, S[i][j]);
            #pragma unroll
            for (int off = 8; off; off >>= 1)
                mx = fmaxf(mx, __shfl_xor_sync(0xFFFFFFFFu, mx, off));
            float mn = fmaxf(m[i], mx);
            float corr = __expf(m[i] - mn);
            float ssum = 0.f;
            #pragma unroll
            for (int j = 0; j < 4; j++) {
                float p = __expf(S[i][j] - mn);
                Ps[ty + 16 * i][tx + 16 * j] = p;
                ssum += p;
            }
            #pragma unroll
            for (int off = 8; off; off >>= 1)
                ssum += __shfl_xor_sync(0xFFFFFFFFu, ssum, off);
            l[i] = l[i] * corr + ssum;
            m[i] = mn;
            #pragma unroll
            for (int j = 0; j < 4; j++) O[i][j] *= corr;
        }
        __syncthreads();   // Ps visible to all

        // O += P V
        #pragma unroll 8
        for (int j = 0; j < 64; j++) {
            float p[4], v[4];
            #pragma unroll
            for (int i = 0; i < 4; i++) {
                p[i] = Ps[ty + 16 * i][j];
                v[i] = Vs[j][tx + 16 * i];
            }
            #pragma unroll
            for (int i = 0; i < 4; i++)
                #pragma unroll
                for (int jj = 0; jj < 4; jj++)
                    O[i][jj] = fmaf(p[i], v[jj], O[i][jj]);
        }
        __syncthreads();   // Vs/Ps reads done before next tile overwrites
    }

    // Normalize and write: y[token][h*64 + d]
    #pragma unroll
    for (int i = 0; i < 4; i++) {
        float invl = 1.f / l[i];
        size_t row = (size_t)(q0 + ty + 16 * i);
        #pragma unroll
        for (int j = 0; j < 4; j++)
            y[row * CC + h * HD + tx + 16 * j] = O[i][j] * invl;
    }
}

// ---------------- SwiGLU elementwise: h1 = silu(h1) * h3 (in place) ----------------
__global__ void swiglu_kernel(float4* __restrict__ h1,
                              const float4* __restrict__ h3, int n4) {
    int i = blockIdx.x * blockDim.x + threadIdx.x;
    if (i < n4) {
        float4 a = h1[i];
        float4 b = h3[i];
        a.x = a.x / (1.f + __expf(-a.x)) * b.x;
        a.y = a.y / (1.f + __expf(-a.y)) * b.y;
        a.z = a.z / (1.f + __expf(-a.z)) * b.z;
        a.w = a.w / (1.f + __expf(-a.w)) * b.w;
        h1[i] = a;
    }
}

// ---------------- launch ----------------
extern "C" void kernel_launch(void* const* d_in, const int* in_sizes, int n_in,
                              void* d_out, int out_size) {
    const float* x           = (const float*)d_in[0];
    const float* attn_norm_w = (const float*)d_in[1];
    const float* ffn_norm_w  = (const float*)d_in[2];
    const float* c_attn_w    = (const float*)d_in[3];
    const float* c_proj_w    = (const float*)d_in[4];
    const float* w1          = (const float*)d_in[5];
    const float* w2          = (const float*)d_in[6];
    const float* w3          = (const float*)d_in[7];
    float* out = (float*)d_out;

    float *xn, *qkv, *yb, *x1, *h1, *h3;
    cudaGetSymbolAddress((void**)&xn,  g_xn);
    cudaGetSymbolAddress((void**)&qkv, g_qkv);
    cudaGetSymbolAddress((void**)&yb,  g_y);
    cudaGetSymbolAddress((void**)&x1,  g_x1);
    cudaGetSymbolAddress((void**)&h1,  g_h1);
    cudaGetSymbolAddress((void**)&h3,  g_h3);

    const int attn_smem = (3 * 64 * 65 + 64 * 64) * (int)sizeof(float);  // 66304 B
    cudaFuncSetAttribute(attn_kernel, cudaFuncAttributeMaxDynamicSharedMemorySize,
                         attn_smem);

    // 1) xn = rmsnorm(x, attn_norm_w)
    rmsnorm_kernel<<<TT, 256>>>(x, attn_norm_w, xn, CC);

    // 2) qkv = xn @ c_attn_w^T       [4096, 3072]
    sgemm_nt<<<dim3(3 * CC / BN, TT / BM), 256>>>(xn, c_attn_w, qkv, TT, 3 * CC, CC, nullptr);

    // 3) y = causal_attention(qkv)   [4096, 1024]
    attn_kernel<<<dim3(TT / 64, NH), 256, attn_smem>>>(qkv, yb);

    // 4) x1 = y @ c_proj_w^T + x
    sgemm_nt<<<dim3(CC / BN, TT / BM), 256>>>(yb, c_proj_w, x1, TT, CC, CC, x);

    // 5) xn = rmsnorm(x1, ffn_norm_w)
    rmsnorm_kernel<<<TT, 256>>>(x1, ffn_norm_w, xn, CC);

    // 6) h1 = xn @ w1^T ; h3 = xn @ w3^T     [4096, 4096]
    sgemm_nt<<<dim3(HF / BN, TT / BM), 256>>>(xn, w1, h1, TT, HF, CC, nullptr);
    sgemm_nt<<<dim3(HF / BN, TT / BM), 256>>>(xn, w3, h3, TT, HF, CC, nullptr);

    // 7) h1 = silu(h1) * h3
    {
        int n4 = TT * HF / 4;
        swiglu_kernel<<<n4 / 256, 256>>>((float4*)h1, (const float4*)h3, n4);
    }

    // 8) out = h1 @ w2^T + x1
    sgemm_nt<<<dim3(CC / BN, TT / BM), 256>>>(h1, w2, out, TT, CC, HF, x1);
}

// round 3
// speedup vs baseline: 1.6252x; 1.6252x over previous
#include <cuda_runtime.h>
#include <cuda_bf16.h>
#include <cstdint>
#include <math.h>

// Problem dims (fixed by the reference)
#define TT 4096
#define CC 1024
#define HF 4096
#define NH 16
#define HD 64

// ---------------- scratch (device globals: allocation-free) ----------------
__device__ float g_xn [(size_t)TT * CC];
__device__ float g_qkv[(size_t)TT * 3 * CC];
__device__ float g_y  [(size_t)TT * CC];
__device__ float g_x1 [(size_t)TT * CC];
__device__ float g_h1 [(size_t)TT * HF];
__device__ float g_h3 [(size_t)TT * HF];

// ================= bf16 split helpers =================
__device__ __forceinline__ uint32_t pack_bf16(float a, float b) {
    uint16_t ha = __bfloat16_as_ushort(__float2bfloat16_rn(a));
    uint16_t hb = __bfloat16_as_ushort(__float2bfloat16_rn(b));
    return (uint32_t)ha | ((uint32_t)hb << 16);
}

// mma.sync m16n8k16 row.col bf16 -> fp32 (family-common, works on sm_103)
__device__ __forceinline__ void mma_bf16(float* c, const uint32_t* a, const uint32_t* b) {
    asm volatile(
        "mma.sync.aligned.m16n8k16.row.col.f32.bf16.bf16.f32 "
        "{%0,%1,%2,%3}, {%4,%5,%6,%7}, {%8,%9}, {%0,%1,%2,%3};"
        : "+f"(c[0]), "+f"(c[1]), "+f"(c[2]), "+f"(c[3])
        : "r"(a[0]), "r"(a[1]), "r"(a[2]), "r"(a[3]), "r"(b[0]), "r"(b[1]));
}

// ================= bf16-split tensor-core GEMM =================
// C[M,N] = A[M,K] * B[N,K]^T (+ add[M,N]), fp32 in/out.
// 3-term split: D = Ah*Bh + Ah*Bl + Al*Bh  (error ~2^-16, fp32-class)
// 128x128x32 CTA tile, 256 threads (2x4 warps, 64x32 warp tile), double-buffered.
#define TROW 80                          // padded row stride in bytes (40 bf16)
#define TILE_BYTES (128 * TROW)          // 10240
#define STAGE_BYTES (4 * TILE_BYTES)     // Ah, Al, Bh, Bl = 40960
#define GEMM_SMEM (2 * STAGE_BYTES)      // 81920

__global__ void __launch_bounds__(256)
gemm_bf16s(const float* __restrict__ A, const float* __restrict__ B,
           float* __restrict__ C, int M, int N, int K,
           const float* __restrict__ add) {
    extern __shared__ char smem[];

    const int tid  = threadIdx.x;
    const int warp = tid >> 5;
    const int lane = tid & 31;
    const int g = lane >> 2;     // fragment group row 0..7
    const int t = lane & 3;      // fragment col pair 0..3
    const int wm = warp >> 2;    // 0..1
    const int wn = warp & 3;     // 0..3
    const int m0 = wm * 64;
    const int n0 = wn * 32;
    const int bm = blockIdx.y * 128;
    const int bn = blockIdx.x * 128;

    float acc[4][4][4];
    #pragma unroll
    for (int i = 0; i < 4; i++)
        #pragma unroll
        for (int j = 0; j < 4; j++)
            #pragma unroll
            for (int r = 0; r < 4; r++) acc[i][j][r] = 0.f;

    // per-thread gmem slots: A slots tid+u*256, B slots tid+u*256 (1024 float4 each)
    float4 va[4], vb[4];

    const int nc = K >> 5;  // chunks of K=32

    // ---- prologue: load + store chunk 0
    {
        #pragma unroll
        for (int u = 0; u < 4; u++) {
            int s = tid + u * 256;
            int row = s >> 3, q = s & 7;
            va[u] = *(const float4*)(A + (size_t)(bm + row) * K + q * 4);
            vb[u] = *(const float4*)(B + (size_t)(bn + row) * K + q * 4);
        }
        char* base = smem;
        #pragma unroll
        for (int u = 0; u < 4; u++) {
            int s = tid + u * 256;
            int row = s >> 3, q = s & 7;
            uint32_t off = (uint32_t)row * TROW + (uint32_t)q * 8;
            float4 v = va[u];
            uint32_t h0 = pack_bf16(v.x, v.y), h1 = pack_bf16(v.z, v.w);
            float lx = v.x - __bfloat162float(__float2bfloat16_rn(v.x));
            float ly = v.y - __bfloat162float(__float2bfloat16_rn(v.y));
            float lz = v.z - __bfloat162float(__float2bfloat16_rn(v.z));
            float lw = v.w - __bfloat162float(__float2bfloat16_rn(v.w));
            *(uint2*)(base + off)              = make_uint2(h0, h1);
            *(uint2*)(base + TILE_BYTES + off) = make_uint2(pack_bf16(lx, ly), pack_bf16(lz, lw));
            v = vb[u];
            h0 = pack_bf16(v.x, v.y); h1 = pack_bf16(v.z, v.w);
            lx = v.x - __bfloat162float(__float2bfloat16_rn(v.x));
            ly = v.y - __bfloat162float(__float2bfloat16_rn(v.y));
            lz = v.z - __bfloat162float(__float2bfloat16_rn(v.z));
            lw = v.w - __bfloat162float(__float2bfloat16_rn(v.w));
            *(uint2*)(base + 2 * TILE_BYTES + off) = make_uint2(h0, h1);
            *(uint2*)(base + 3 * TILE_BYTES + off) = make_uint2(pack_bf16(lx, ly), pack_bf16(lz, lw));
        }
    }
    __syncthreads();

    for (int c = 0; c < nc; c++) {
        const int cur = c & 1;
        const bool more = (c + 1 < nc);

        // prefetch next chunk into registers
        if (more) {
            int k0 = (c + 1) << 5;
            #pragma unroll
            for (int u = 0; u < 4; u++) {
                int s = tid + u * 256;
                int row = s >> 3, q = s & 7;
                va[u] = *(const float4*)(A + (size_t)(bm + row) * K + k0 + q * 4);
                vb[u] = *(const float4*)(B + (size_t)(bn + row) * K + k0 + q * 4);
            }
        }

        // ---- compute on stage cur
        {
            const char* base = smem + cur * STAGE_BYTES;
            const char* Ah = base;
            const char* Al = base + TILE_BYTES;
            const char* Bh = base + 2 * TILE_BYTES;
            const char* Bl = base + 3 * TILE_BYTES;

            #pragma unroll
            for (int ks = 0; ks < 2; ks++) {
                const int kb = ks * 16;                 // bf16 col offset
                const uint32_t kc = (uint32_t)(kb + t * 2) * 2;  // byte offset of k pair

                uint32_t bhf[4][2], blf[4][2];
                #pragma unroll
                for (int j = 0; j < 4; j++) {
                    uint32_t o0 = (uint32_t)(n0 + j * 8 + g) * TROW + kc;
                    bhf[j][0] = *(const uint32_t*)(Bh + o0);
                    bhf[j][1] = *(const uint32_t*)(Bh + o0 + 16);
                    blf[j][0] = *(const uint32_t*)(Bl + o0);
                    blf[j][1] = *(const uint32_t*)(Bl + o0 + 16);
                }
                #pragma unroll
                for (int i = 0; i < 4; i++) {
                    uint32_t o0 = (uint32_t)(m0 + i * 16 + g) * TROW + kc;
                    uint32_t o1 = o0 + 8 * TROW;
                    uint32_t ahf[4], alf[4];
                    ahf[0] = *(const uint32_t*)(Ah + o0);
                    ahf[1] = *(const uint32_t*)(Ah + o1);
                    ahf[2] = *(const uint32_t*)(Ah + o0 + 16);
                    ahf[3] = *(const uint32_t*)(Ah + o1 + 16);
                    alf[0] = *(const uint32_t*)(Al + o0);
                    alf[1] = *(const uint32_t*)(Al + o1);
                    alf[2] = *(const uint32_t*)(Al + o0 + 16);
                    alf[3] = *(const uint32_t*)(Al + o1 + 16);
                    #pragma unroll
                    for (int j = 0; j < 4; j++) {
                        mma_bf16(acc[i][j], ahf, bhf[j]);
                        mma_bf16(acc[i][j], ahf, blf[j]);
                        mma_bf16(acc[i][j], alf, bhf[j]);
                    }
                }
            }
        }

        // ---- store next chunk into the other stage
        if (more) {
            char* base = smem + (cur ^ 1) * STAGE_BYTES;
            #pragma unroll
            for (int u = 0; u < 4; u++) {
                int s = tid + u * 256;
                int row = s >> 3, q = s & 7;
                uint32_t off = (uint32_t)row * TROW + (uint32_t)q * 8;
                float4 v = va[u];
                uint32_t h0 = pack_bf16(v.x, v.y), h1 = pack_bf16(v.z, v.w);
                float lx = v.x - __bfloat162float(__float2bfloat16_rn(v.x));
                float ly = v.y - __bfloat162float(__float2bfloat16_rn(v.y));
                float lz = v.z - __bfloat162float(__float2bfloat16_rn(v.z));
                float lw = v.w - __bfloat162float(__float2bfloat16_rn(v.w));
                *(uint2*)(base + off)              = make_uint2(h0, h1);
                *(uint2*)(base + TILE_BYTES + off) = make_uint2(pack_bf16(lx, ly), pack_bf16(lz, lw));
                v = vb[u];
                h0 = pack_bf16(v.x, v.y); h1 = pack_bf16(v.z, v.w);
                lx = v.x - __bfloat162float(__float2bfloat16_rn(v.x));
                ly = v.y - __bfloat162float(__float2bfloat16_rn(v.y));
                lz = v.z - __bfloat162float(__float2bfloat16_rn(v.z));
                lw = v.w - __bfloat162float(__float2bfloat16_rn(v.w));
                *(uint2*)(base + 2 * TILE_BYTES + off) = make_uint2(h0, h1);
                *(uint2*)(base + 3 * TILE_BYTES + off) = make_uint2(pack_bf16(lx, ly), pack_bf16(lz, lw));
            }
        }
        __syncthreads();
    }

    // ---- epilogue
    #pragma unroll
    for (int i = 0; i < 4; i++) {
        size_t r0 = (size_t)(bm + m0 + i * 16 + g);
        size_t r1 = r0 + 8;
        #pragma unroll
        for (int j = 0; j < 4; j++) {
            int col = bn + n0 + j * 8 + t * 2;
            float2 v0 = make_float2(acc[i][j][0], acc[i][j][1]);
            float2 v1 = make_float2(acc[i][j][2], acc[i][j][3]);
            if (add) {
                float2 a0 = *(const float2*)(add + r0 * N + col);
                float2 a1 = *(const float2*)(add + r1 * N + col);
                v0.x += a0.x; v0.y += a0.y;
                v1.x += a1.x; v1.y += a1.y;
            }
            *(float2*)(C + r0 * N + col) = v0;
            *(float2*)(C + r1 * N + col) = v1;
        }
    }
}

// ---------------- RMSNorm: one block per row ----------------
__global__ void rmsnorm_kernel(const float* __restrict__ x,
                               const float* __restrict__ w,
                               float* __restrict__ o, int C) {
    int row = blockIdx.x;
    const float* xr = x + (size_t)row * C;
    float s = 0.f;
    for (int i = threadIdx.x; i < C; i += blockDim.x) {
        float v = xr[i];
        s += v * v;
    }
    __shared__ float red[32];
    #pragma unroll
    for (int off = 16; off; off >>= 1) s += __shfl_down_sync(0xFFFFFFFFu, s, off);
    if ((threadIdx.x & 31) == 0) red[threadIdx.x >> 5] = s;
    __syncthreads();
    if (threadIdx.x < 32) {
        float v = (threadIdx.x < (blockDim.x >> 5)) ? red[threadIdx.x] : 0.f;
        #pragma unroll
        for (int off = 16; off; off >>= 1) v += __shfl_down_sync(0xFFFFFFFFu, v, off);
        if (threadIdx.x == 0) red[0] = v;
    }
    __syncthreads();
    float inv = rsqrtf(red[0] / (float)C + 1e-6f);
    for (int i = threadIdx.x; i < C; i += blockDim.x)
        o[(size_t)row * C + i] = xr[i] * inv * w[i];
}

// ---------------- Flash attention (causal), fp32 (unchanged, passing) ----------------
__global__ void __launch_bounds__(256)
attn_kernel(const float* __restrict__ qkv, float* __restrict__ y) {
    extern __shared__ float sm[];
    float (*Qt)[65] = (float(*)[65])(sm);
    float (*Kt)[65] = (float(*)[65])(sm + 64 * 65);
    float (*Ps)[65] = (float(*)[65])(sm + 2 * 64 * 65);
    float (*Vs)[64] = (float(*)[64])(sm + 3 * 64 * 65);

    const int qt = blockIdx.x;
    const int h  = blockIdx.y;
    const int tid = threadIdx.x;
    const int tx = tid & 15;
    const int ty = tid >> 4;
    const int C3 = 3 * CC;
    const int q0 = qt * 64;
    const float scale = 0.125f;

    for (int f = tid; f < 64 * 64; f += 256) {
        int r = f >> 6, d = f & 63;
        Qt[d][r] = qkv[(size_t)(q0 + r) * C3 + h * HD + d];
    }

    float m[4], l[4], O[4][4];
    #pragma unroll
    for (int i = 0; i < 4; i++) {
        m[i] = -1e30f; l[i] = 0.f;
        #pragma unroll
        for (int j = 0; j < 4; j++) O[i][j] = 0.f;
    }
    __syncthreads();

    for (int kt = 0; kt <= qt; kt++) {
        const int k0 = kt * 64;
        for (int f = tid; f < 64 * 64; f += 256) {
            int r = f >> 6, d = f & 63;
            Kt[d][r] = qkv[(size_t)(k0 + r) * C3 + CC     + h * HD + d];
            Vs[r][d] = qkv[(size_t)(k0 + r) * C3 + 2 * CC + h * HD + d];
        }
        __syncthreads();

        float S[4][4];
        #pragma unroll
        for (int i = 0; i < 4; i++)
            #pragma unroll
            for (int j = 0; j < 4; j++) S[i][j] = 0.f;

        #pragma unroll 8
        for (int k = 0; k < HD; k++) {
            float q[4], kk[4];
            #pragma unroll
            for (int i = 0; i < 4; i++) {
                q[i]  = Qt[k][ty + 16 * i];
                kk[i] = Kt[k][tx + 16 * i];
            }
            #pragma unroll
            for (int i = 0; i < 4; i++)
                #pragma unroll
                for (int j = 0; j < 4; j++)
                    S[i][j] = fmaf(q[i], kk[j], S[i][j]);
        }

        if (kt == qt) {
            #pragma unroll
            for (int i = 0; i < 4; i++)
                #pragma unroll
                for (int j = 0; j < 4; j++) {
                    int rr = ty + 16 * i, cc = tx + 16 * j;
                    S[i][j] = (cc <= rr) ? S[i][j] * scale : -1e30f;
                }
        } else {
            #pragma unroll
            for (int i = 0; i < 4; i++)
                #pragma unroll
                for (int j = 0; j < 4; j++) S[i][j] *= scale;
        }

        #pragma unroll
        for (int i = 0; i < 4; i++) {
            float mx = S[i][0];
            #pragma unroll
            for (int j = 1; j < 4; j++) mx = fmaxf(mx, S[i][j]);
            #pragma unroll
            for (int off = 8; off; off >>= 1)
                mx = fmaxf(mx, __shfl_xor_sync(0xFFFFFFFFu, mx, off));
            float mn = fmaxf(m[i], mx);
            float corr = __expf(m[i] - mn);
            float ssum = 0.f;
            #pragma unroll
            for (int j = 0; j < 4; j++) {
                float p = __expf(S[i][j] - mn);
                Ps[ty + 16 * i][tx + 16 * j] = p;
                ssum += p;
            }
            #pragma unroll
            for (int off = 8; off; off >>= 1)
                ssum += __shfl_xor_sync(0xFFFFFFFFu, ssum, off);
            l[i] = l[i] * corr + ssum;
            m[i] = mn;
            #pragma unroll
            for (int j = 0; j < 4; j++) O[i][j] *= corr;
        }
        __syncthreads();

        #pragma unroll 8
        for (int j = 0; j < 64; j++) {
            float p[4], v[4];
            #pragma unroll
            for (int i = 0; i < 4; i++) {
                p[i] = Ps[ty + 16 * i][j];
                v[i] = Vs[j][tx + 16 * i];
            }
            #pragma unroll
            for (int i = 0; i < 4; i++)
                #pragma unroll
                for (int jj = 0; jj < 4; jj++)
                    O[i][jj] = fmaf(p[i], v[jj], O[i][jj]);
        }
        __syncthreads();
    }

    #pragma unroll
    for (int i = 0; i < 4; i++) {
        float invl = 1.f / l[i];
        size_t row = (size_t)(q0 + ty + 16 * i);
        #pragma unroll
        for (int j = 0; j < 4; j++)
            y[row * CC + h * HD + tx + 16 * j] = O[i][j] * invl;
    }
}

// ---------------- SwiGLU elementwise: h1 = silu(h1) * h3 (in place) ----------------
__global__ void swiglu_kernel(float4* __restrict__ h1,
                              const float4* __restrict__ h3, int n4) {
    int i = blockIdx.x * blockDim.x + threadIdx.x;
    if (i < n4) {
        float4 a = h1[i];
        float4 b = h3[i];
        a.x = a.x / (1.f + __expf(-a.x)) * b.x;
        a.y = a.y / (1.f + __expf(-a.y)) * b.y;
        a.z = a.z / (1.f + __expf(-a.z)) * b.z;
        a.w = a.w / (1.f + __expf(-a.w)) * b.w;
        h1[i] = a;
    }
}

// ---------------- launch ----------------
extern "C" void kernel_launch(void* const* d_in, const int* in_sizes, int n_in,
                              void* d_out, int out_size) {
    const float* x           = (const float*)d_in[0];
    const float* attn_norm_w = (const float*)d_in[1];
    const float* ffn_norm_w  = (const float*)d_in[2];
    const float* c_attn_w    = (const float*)d_in[3];
    const float* c_proj_w    = (const float*)d_in[4];
    const float* w1          = (const float*)d_in[5];
    const float* w2          = (const float*)d_in[6];
    const float* w3          = (const float*)d_in[7];
    float* out = (float*)d_out;

    float *xn, *qkv, *yb, *x1, *h1, *h3;
    cudaGetSymbolAddress((void**)&xn,  g_xn);
    cudaGetSymbolAddress((void**)&qkv, g_qkv);
    cudaGetSymbolAddress((void**)&yb,  g_y);
    cudaGetSymbolAddress((void**)&x1,  g_x1);
    cudaGetSymbolAddress((void**)&h1,  g_h1);
    cudaGetSymbolAddress((void**)&h3,  g_h3);

    const int attn_smem = (3 * 64 * 65 + 64 * 64) * (int)sizeof(float);
    cudaFuncSetAttribute(attn_kernel, cudaFuncAttributeMaxDynamicSharedMemorySize, attn_smem);
    cudaFuncSetAttribute(gemm_bf16s, cudaFuncAttributeMaxDynamicSharedMemorySize, GEMM_SMEM);

    // 1) xn = rmsnorm(x, attn_norm_w)
    rmsnorm_kernel<<<TT, 256>>>(x, attn_norm_w, xn, CC);

    // 2) qkv = xn @ c_attn_w^T       [4096, 3072]
    gemm_bf16s<<<dim3(3 * CC / 128, TT / 128), 256, GEMM_SMEM>>>(xn, c_attn_w, qkv, TT, 3 * CC, CC, nullptr);

    // 3) y = causal_attention(qkv)   [4096, 1024]
    attn_kernel<<<dim3(TT / 64, NH), 256, attn_smem>>>(qkv, yb);

    // 4) x1 = y @ c_proj_w^T + x
    gemm_bf16s<<<dim3(CC / 128, TT / 128), 256, GEMM_SMEM>>>(yb, c_proj_w, x1, TT, CC, CC, x);

    // 5) xn = rmsnorm(x1, ffn_norm_w)
    rmsnorm_kernel<<<TT, 256>>>(x1, ffn_norm_w, xn, CC);

    // 6) h1 = xn @ w1^T ; h3 = xn @ w3^T     [4096, 4096]
    gemm_bf16s<<<dim3(HF / 128, TT / 128), 256, GEMM_SMEM>>>(xn, w1, h1, TT, HF, CC, nullptr);
    gemm_bf16s<<<dim3(HF / 128, TT / 128), 256, GEMM_SMEM>>>(xn, w3, h3, TT, HF, CC, nullptr);

    // 7) h1 = silu(h1) * h3
    {
        int n4 = TT * HF / 4;
        swiglu_kernel<<<n4 / 256, 256>>>((float4*)h1, (const float4*)h3, n4);
    }

    // 8) out = h1 @ w2^T + x1
    gemm_bf16s<<<dim3(CC / 128, TT / 128), 256, GEMM_SMEM>>>(h1, w2, out, TT, CC, HF, x1);
}

// round 4
// speedup vs baseline: 2.3728x; 1.4600x over previous
#include <cuda_runtime.h>
#include <cuda_bf16.h>
#include <cstdint>
#include <math.h>

// Problem dims (fixed by the reference)
#define TT 4096
#define CC 1024
#define HF 4096
#define NH 16
#define HD 64

// ---------------- scratch (device globals: allocation-free) ----------------
__device__ float g_xn [(size_t)TT * CC];
__device__ float g_qkv[(size_t)TT * 3 * CC];
__device__ float g_y  [(size_t)TT * CC];
__device__ float g_x1 [(size_t)TT * CC];
__device__ float g_h1 [(size_t)TT * HF];
__device__ float g_h3 [(size_t)TT * HF];

// ================= helpers =================
__device__ __forceinline__ uint32_t smem_u32(const void* p) {
    uint32_t a;
    asm("{ .reg .u64 t; cvta.to.shared.u64 t, %1; cvt.u32.u64 %0, t; }" : "=r"(a) : "l"(p));
    return a;
}
__device__ __forceinline__ uint32_t pack_bf16(float a, float b) {
    uint16_t ha = __bfloat16_as_ushort(__float2bfloat16_rn(a));
    uint16_t hb = __bfloat16_as_ushort(__float2bfloat16_rn(b));
    return (uint32_t)ha | ((uint32_t)hb << 16);
}
__device__ __forceinline__ float bf16r(float x) {
    return __bfloat162float(__float2bfloat16_rn(x));
}
__device__ __forceinline__ float ex2(float x) {
    float r;
    asm("ex2.approx.f32 %0, %1;" : "=f"(r) : "f"(x));
    return r;
}
// mma.sync m16n8k16 row.col bf16 -> fp32 (family-common on sm_103)
__device__ __forceinline__ void mma_bf16(float* c, const uint32_t* a, const uint32_t* b) {
    asm volatile(
        "mma.sync.aligned.m16n8k16.row.col.f32.bf16.bf16.f32 "
        "{%0,%1,%2,%3}, {%4,%5,%6,%7}, {%8,%9}, {%0,%1,%2,%3};"
        : "+f"(c[0]), "+f"(c[1]), "+f"(c[2]), "+f"(c[3])
        : "r"(a[0]), "r"(a[1]), "r"(a[2]), "r"(a[3]), "r"(b[0]), "r"(b[1]));
}
__device__ __forceinline__ void ldsm_x4_trans(uint32_t addr, uint32_t& b0, uint32_t& b1,
                                              uint32_t& b2, uint32_t& b3) {
    asm volatile("ldmatrix.sync.aligned.m8n8.x4.trans.shared.b16 {%0,%1,%2,%3}, [%4];"
                 : "=r"(b0), "=r"(b1), "=r"(b2), "=r"(b3) : "r"(addr));
}
__device__ __forceinline__ void split4(float4 v, uint2& h, uint2& l) {
    float hx = bf16r(v.x), hy = bf16r(v.y), hz = bf16r(v.z), hw = bf16r(v.w);
    h = make_uint2(pack_bf16(v.x, v.y), pack_bf16(v.z, v.w));
    l = make_uint2(pack_bf16(v.x - hx, v.y - hy), pack_bf16(v.z - hz, v.w - hw));
}

// ================= bf16-split tensor-core GEMM (unchanged, passing) =================
#define TROW 80
#define TILE_BYTES (128 * TROW)
#define STAGE_BYTES (4 * TILE_BYTES)
#define GEMM_SMEM (2 * STAGE_BYTES)

__global__ void __launch_bounds__(256)
gemm_bf16s(const float* __restrict__ A, const float* __restrict__ B,
           float* __restrict__ C, int M, int N, int K,
           const float* __restrict__ add) {
    extern __shared__ char smem[];

    const int tid  = threadIdx.x;
    const int warp = tid >> 5;
    const int lane = tid & 31;
    const int g = lane >> 2;
    const int t = lane & 3;
    const int wm = warp >> 2;
    const int wn = warp & 3;
    const int m0 = wm * 64;
    const int n0 = wn * 32;
    const int bm = blockIdx.y * 128;
    const int bn = blockIdx.x * 128;

    float acc[4][4][4];
    #pragma unroll
    for (int i = 0; i < 4; i++)
        #pragma unroll
        for (int j = 0; j < 4; j++)
            #pragma unroll
            for (int r = 0; r < 4; r++) acc[i][j][r] = 0.f;

    float4 va[4], vb[4];
    const int nc = K >> 5;

    {
        #pragma unroll
        for (int u = 0; u < 4; u++) {
            int s = tid + u * 256;
            int row = s >> 3, q = s & 7;
            va[u] = *(const float4*)(A + (size_t)(bm + row) * K + q * 4);
            vb[u] = *(const float4*)(B + (size_t)(bn + row) * K + q * 4);
        }
        char* base = smem;
        #pragma unroll
        for (int u = 0; u < 4; u++) {
            int s = tid + u * 256;
            int row = s >> 3, q = s & 7;
            uint32_t off = (uint32_t)row * TROW + (uint32_t)q * 8;
            uint2 h, l;
            split4(va[u], h, l);
            *(uint2*)(base + off)              = h;
            *(uint2*)(base + TILE_BYTES + off) = l;
            split4(vb[u], h, l);
            *(uint2*)(base + 2 * TILE_BYTES + off) = h;
            *(uint2*)(base + 3 * TILE_BYTES + off) = l;
        }
    }
    __syncthreads();

    for (int c = 0; c < nc; c++) {
        const int cur = c & 1;
        const bool more = (c + 1 < nc);

        if (more) {
            int k0 = (c + 1) << 5;
            #pragma unroll
            for (int u = 0; u < 4; u++) {
                int s = tid + u * 256;
                int row = s >> 3, q = s & 7;
                va[u] = *(const float4*)(A + (size_t)(bm + row) * K + k0 + q * 4);
                vb[u] = *(const float4*)(B + (size_t)(bn + row) * K + k0 + q * 4);
            }
        }

        {
            const char* base = smem + cur * STAGE_BYTES;
            const char* Ah = base;
            const char* Al = base + TILE_BYTES;
            const char* Bh = base + 2 * TILE_BYTES;
            const char* Bl = base + 3 * TILE_BYTES;

            #pragma unroll
            for (int ks = 0; ks < 2; ks++) {
                const int kb = ks * 16;
                const uint32_t kc = (uint32_t)(kb + t * 2) * 2;

                uint32_t bhf[4][2], blf[4][2];
                #pragma unroll
                for (int j = 0; j < 4; j++) {
                    uint32_t o0 = (uint32_t)(n0 + j * 8 + g) * TROW + kc;
                    bhf[j][0] = *(const uint32_t*)(Bh + o0);
                    bhf[j][1] = *(const uint32_t*)(Bh + o0 + 16);
                    blf[j][0] = *(const uint32_t*)(Bl + o0);
                    blf[j][1] = *(const uint32_t*)(Bl + o0 + 16);
                }
                #pragma unroll
                for (int i = 0; i < 4; i++) {
                    uint32_t o0 = (uint32_t)(m0 + i * 16 + g) * TROW + kc;
                    uint32_t o1 = o0 + 8 * TROW;
                    uint32_t ahf[4], alf[4];
                    ahf[0] = *(const uint32_t*)(Ah + o0);
                    ahf[1] = *(const uint32_t*)(Ah + o1);
                    ahf[2] = *(const uint32_t*)(Ah + o0 + 16);
                    ahf[3] = *(const uint32_t*)(Ah + o1 + 16);
                    alf[0] = *(const uint32_t*)(Al + o0);
                    alf[1] = *(const uint32_t*)(Al + o1);
                    alf[2] = *(const uint32_t*)(Al + o0 + 16);
                    alf[3] = *(const uint32_t*)(Al + o1 + 16);
                    #pragma unroll
                    for (int j = 0; j < 4; j++) {
                        mma_bf16(acc[i][j], ahf, bhf[j]);
                        mma_bf16(acc[i][j], ahf, blf[j]);
                        mma_bf16(acc[i][j], alf, bhf[j]);
                    }
                }
            }
        }

        if (more) {
            char* base = smem + (cur ^ 1) * STAGE_BYTES;
            #pragma unroll
            for (int u = 0; u < 4; u++) {
                int s = tid + u * 256;
                int row = s >> 3, q = s & 7;
                uint32_t off = (uint32_t)row * TROW + (uint32_t)q * 8;
                uint2 h, l;
                split4(va[u], h, l);
                *(uint2*)(base + off)              = h;
                *(uint2*)(base + TILE_BYTES + off) = l;
                split4(vb[u], h, l);
                *(uint2*)(base + 2 * TILE_BYTES + off) = h;
                *(uint2*)(base + 3 * TILE_BYTES + off) = l;
            }
        }
        __syncthreads();
    }

    #pragma unroll
    for (int i = 0; i < 4; i++) {
        size_t r0 = (size_t)(bm + m0 + i * 16 + g);
        size_t r1 = r0 + 8;
        #pragma unroll
        for (int j = 0; j < 4; j++) {
            int col = bn + n0 + j * 8 + t * 2;
            float2 v0 = make_float2(acc[i][j][0], acc[i][j][1]);
            float2 v1 = make_float2(acc[i][j][2], acc[i][j][3]);
            if (add) {
                float2 a0 = *(const float2*)(add + r0 * N + col);
                float2 a1 = *(const float2*)(add + r1 * N + col);
                v0.x += a0.x; v0.y += a0.y;
                v1.x += a1.x; v1.y += a1.y;
            }
            *(float2*)(C + r0 * N + col) = v0;
            *(float2*)(C + r1 * N + col) = v1;
        }
    }
}

// ================= MMA flash attention (causal), bf16-split =================
// CTA: 128 q-rows x 1 head. 8 warps, warp w owns q rows [w*16, w*16+16).
// ktile = 64 keys, K/V double-buffered in smem; S C-frags reused as PV A-frags.
#define ASTR 144                  // smem row stride bytes (64 bf16 + 8 pad)
#define Q_BYTES (128 * ASTR)      // 18432 per Q tensor (hi or lo)
#define KV_BYTES (64 * ASTR)      // 9216 per K/V tensor
#define BUF_BYTES (4 * KV_BYTES)  // KH, KL, VH, VL = 36864
#define ATTN_SMEM (2 * Q_BYTES + 2 * BUF_BYTES)  // 110592

__global__ void __launch_bounds__(256)
attn_mma(const float* __restrict__ qkv, float* __restrict__ y) {
    extern __shared__ char sm[];
    const uint32_t sb = smem_u32(sm);
    const int tid  = threadIdx.x;
    const int w    = tid >> 5;
    const int lane = tid & 31;
    const int g = lane >> 2, t = lane & 3;
    const int qt = 31 - (int)blockIdx.x;     // reversed: longest tiles first
    const int h  = blockIdx.y;
    const int q0 = qt * 128;
    const int C3 = 3 * CC;
    const int qko = h * HD;
    const uint32_t QH = 0, QL = Q_BYTES;
    const uint32_t BUF0 = 2 * Q_BYTES;

    // ---- load Q tile (scaled by log2e/8 BEFORE split), hi/lo STS
    const float qs = 1.4426950408889634f * 0.125f;
    #pragma unroll
    for (int u = 0; u < 8; u++) {
        int idx = tid + u * 256;
        int row = idx >> 4, dg = idx & 15;
        float4 v = *(const float4*)(qkv + (size_t)(q0 + row) * C3 + qko + dg * 4);
        v.x *= qs; v.y *= qs; v.z *= qs; v.w *= qs;
        uint32_t off = (uint32_t)row * ASTR + (uint32_t)dg * 8;
        uint2 hh, ll;
        split4(v, hh, ll);
        *(uint2*)(sm + QH + off) = hh;
        *(uint2*)(sm + QL + off) = ll;
    }
    __syncthreads();

    // ---- persistent Q A-fragments (per warp, all 4 k-steps, hi+lo)
    uint32_t qh[4][4], ql[4][4];
    {
        uint32_t rb = (uint32_t)(w * 16 + g) * ASTR + (uint32_t)t * 4;
        #pragma unroll
        for (int ks = 0; ks < 4; ks++) {
            uint32_t o = rb + ks * 32;
            qh[ks][0] = *(const uint32_t*)(sm + QH + o);
            qh[ks][1] = *(const uint32_t*)(sm + QH + o + 8 * ASTR);
            qh[ks][2] = *(const uint32_t*)(sm + QH + o + 16);
            qh[ks][3] = *(const uint32_t*)(sm + QH + o + 8 * ASTR + 16);
            ql[ks][0] = *(const uint32_t*)(sm + QL + o);
            ql[ks][1] = *(const uint32_t*)(sm + QL + o + 8 * ASTR);
            ql[ks][2] = *(const uint32_t*)(sm + QL + o + 16);
            ql[ks][3] = *(const uint32_t*)(sm + QL + o + 8 * ASTR + 16);
        }
    }

    // ---- prologue: load K/V tile 0 into buffer 0
    {
        #pragma unroll
        for (int u = 0; u < 4; u++) {
            int idx = tid + u * 256;
            int row = idx >> 4, dg = idx & 15;
            float4 kvv = *(const float4*)(qkv + (size_t)row * C3 + CC + qko + dg * 4);
            float4 vvv = *(const float4*)(qkv + (size_t)row * C3 + 2 * CC + qko + dg * 4);
            uint32_t off = BUF0 + (uint32_t)row * ASTR + (uint32_t)dg * 8;
            uint2 hh, ll;
            split4(kvv, hh, ll);
            *(uint2*)(sm + off)            = hh;
            *(uint2*)(sm + off + KV_BYTES) = ll;
            split4(vvv, hh, ll);
            *(uint2*)(sm + off + 2 * KV_BYTES) = hh;
            *(uint2*)(sm + off + 3 * KV_BYTES) = ll;
        }
    }
    __syncthreads();

    float O[8][4];
    #pragma unroll
    for (int nf = 0; nf < 8; nf++)
        #pragma unroll
        for (int r = 0; r < 4; r++) O[nf][r] = 0.f;
    float m0 = -1e30f, m1 = -1e30f, l0 = 0.f, l1 = 0.f;

    const int nk = 2 * qt + 2;
    const int r0g = q0 + w * 16 + g;          // this thread's first q row
    // ldmatrix per-lane offset within a V tensor
    const int blk = lane >> 3, lr = lane & 7;
    const uint32_t ldsm_off = (uint32_t)((blk & 1) * 8 + lr) * ASTR + (uint32_t)(blk >> 1) * 16;

    for (int kt = 0; kt < nk; kt++) {
        const uint32_t kb = BUF0 + (uint32_t)(kt & 1) * BUF_BYTES;
        const bool more = (kt + 1 < nk);

        // prefetch next K/V into regs
        float4 pk[4], pv[4];
        if (more) {
            int k0n = (kt + 1) * 64;
            #pragma unroll
            for (int u = 0; u < 4; u++) {
                int idx = tid + u * 256;
                int row = idx >> 4, dg = idx & 15;
                pk[u] = *(const float4*)(qkv + (size_t)(k0n + row) * C3 + CC + qko + dg * 4);
                pv[u] = *(const float4*)(qkv + (size_t)(k0n + row) * C3 + 2 * CC + qko + dg * 4);
            }
        }

        // ---- S = Q K^T (3-term split)
        float S[8][4];
        #pragma unroll
        for (int nf = 0; nf < 8; nf++)
            #pragma unroll
            for (int r = 0; r < 4; r++) S[nf][r] = 0.f;

        #pragma unroll
        for (int ks = 0; ks < 4; ks++) {
            #pragma unroll
            for (int nf = 0; nf < 8; nf++) {
                uint32_t ko = kb + (uint32_t)(nf * 8 + g) * ASTR + (uint32_t)(ks * 32 + t * 4);
                uint32_t bh[2], bl[2];
                bh[0] = *(const uint32_t*)(sm + ko);
                bh[1] = *(const uint32_t*)(sm + ko + 16);
                bl[0] = *(const uint32_t*)(sm + ko + KV_BYTES);
                bl[1] = *(const uint32_t*)(sm + ko + KV_BYTES + 16);
                mma_bf16(S[nf], qh[ks], bh);
                mma_bf16(S[nf], ql[ks], bh);
                mma_bf16(S[nf], qh[ks], bl);
            }
        }

        // ---- causal mask (only on/after the diagonal)
        if (kt >= 2 * qt) {
            int k0 = kt * 64;
            #pragma unroll
            for (int nf = 0; nf < 8; nf++) {
                int c = k0 + nf * 8 + 2 * t;
                if (c     > r0g)     S[nf][0] = -1e30f;
                if (c + 1 > r0g)     S[nf][1] = -1e30f;
                if (c     > r0g + 8) S[nf][2] = -1e30f;
                if (c + 1 > r0g + 8) S[nf][3] = -1e30f;
            }
        }

        // ---- online softmax (base-2; scale folded into Q)
        float rm0 = -1e30f, rm1 = -1e30f;
        #pragma unroll
        for (int nf = 0; nf < 8; nf++) {
            rm0 = fmaxf(rm0, fmaxf(S[nf][0], S[nf][1]));
            rm1 = fmaxf(rm1, fmaxf(S[nf][2], S[nf][3]));
        }
        rm0 = fmaxf(rm0, __shfl_xor_sync(0xFFFFFFFFu, rm0, 1));
        rm0 = fmaxf(rm0, __shfl_xor_sync(0xFFFFFFFFu, rm0, 2));
        rm1 = fmaxf(rm1, __shfl_xor_sync(0xFFFFFFFFu, rm1, 1));
        rm1 = fmaxf(rm1, __shfl_xor_sync(0xFFFFFFFFu, rm1, 2));
        float m0n = fmaxf(m0, rm0), m1n = fmaxf(m1, rm1);
        float cr0 = ex2(m0 - m0n), cr1 = ex2(m1 - m1n);
        float s0 = 0.f, s1 = 0.f;
        #pragma unroll
        for (int nf = 0; nf < 8; nf++) {
            S[nf][0] = ex2(S[nf][0] - m0n);
            S[nf][1] = ex2(S[nf][1] - m0n);
            S[nf][2] = ex2(S[nf][2] - m1n);
            S[nf][3] = ex2(S[nf][3] - m1n);
            s0 += S[nf][0] + S[nf][1];
            s1 += S[nf][2] + S[nf][3];
        }
        s0 += __shfl_xor_sync(0xFFFFFFFFu, s0, 1);
        s0 += __shfl_xor_sync(0xFFFFFFFFu, s0, 2);
        s1 += __shfl_xor_sync(0xFFFFFFFFu, s1, 1);
        s1 += __shfl_xor_sync(0xFFFFFFFFu, s1, 2);
        l0 = l0 * cr0 + s0;
        l1 = l1 * cr1 + s1;
        m0 = m0n; m1 = m1n;
        #pragma unroll
        for (int nf = 0; nf < 8; nf++) {
            O[nf][0] *= cr0; O[nf][1] *= cr0;
            O[nf][2] *= cr1; O[nf][3] *= cr1;
        }

        // ---- pack P (hi/lo) into PV A-fragments: S C-frag == PV A-frag layout
        uint32_t pah[4][4], pal[4][4];
        #pragma unroll
        for (int ks = 0; ks < 4; ks++) {
            int n0f = 2 * ks, n1f = n0f + 1;
            float p00 = S[n0f][0], p01 = S[n0f][1], p02 = S[n0f][2], p03 = S[n0f][3];
            float p10 = S[n1f][0], p11 = S[n1f][1], p12 = S[n1f][2], p13 = S[n1f][3];
            pah[ks][0] = pack_bf16(p00, p01);
            pah[ks][1] = pack_bf16(p02, p03);
            pah[ks][2] = pack_bf16(p10, p11);
            pah[ks][3] = pack_bf16(p12, p13);
            pal[ks][0] = pack_bf16(p00 - bf16r(p00), p01 - bf16r(p01));
            pal[ks][1] = pack_bf16(p02 - bf16r(p02), p03 - bf16r(p03));
            pal[ks][2] = pack_bf16(p10 - bf16r(p10), p11 - bf16r(p11));
            pal[ks][3] = pack_bf16(p12 - bf16r(p12), p13 - bf16r(p13));
        }

        // ---- store prefetched K/V into the other buffer
        if (more) {
            uint32_t nb = BUF0 + (uint32_t)((kt + 1) & 1) * BUF_BYTES;
            #pragma unroll
            for (int u = 0; u < 4; u++) {
                int idx = tid + u * 256;
                int row = idx >> 4, dg = idx & 15;
                uint32_t off = nb + (uint32_t)row * ASTR + (uint32_t)dg * 8;
                uint2 hh, ll;
                split4(pk[u], hh, ll);
                *(uint2*)(sm + off)            = hh;
                *(uint2*)(sm + off + KV_BYTES) = ll;
                split4(pv[u], hh, ll);
                *(uint2*)(sm + off + 2 * KV_BYTES) = hh;
                *(uint2*)(sm + off + 3 * KV_BYTES) = ll;
            }
        }

        // ---- O += P V (3-term split), V frags via ldmatrix.trans
        {
            const uint32_t vh = sb + kb + 2 * KV_BYTES;
            #pragma unroll
            for (int ks = 0; ks < 4; ks++) {
                uint32_t ka = vh + (uint32_t)(ks * 16) * ASTR + ldsm_off;
                #pragma unroll
                for (int np = 0; np < 4; np++) {
                    uint32_t a = ka + (uint32_t)np * 32;
                    uint32_t b0, b1, b2, b3;
                    ldsm_x4_trans(a, b0, b1, b2, b3);
                    uint32_t bb0[2] = {b0, b1}, bb1[2] = {b2, b3};
                    mma_bf16(O[2 * np],     pah[ks], bb0);
                    mma_bf16(O[2 * np + 1], pah[ks], bb1);
                    mma_bf16(O[2 * np],     pal[ks], bb0);
                    mma_bf16(O[2 * np + 1], pal[ks], bb1);
                    ldsm_x4_trans(a + KV_BYTES, b0, b1, b2, b3);
                    uint32_t cb0[2] = {b0, b1}, cb1[2] = {b2, b3};
                    mma_bf16(O[2 * np],     pah[ks], cb0);
                    mma_bf16(O[2 * np + 1], pah[ks], cb1);
                }
            }
        }
        __syncthreads();
    }

    // ---- epilogue: y[row][h*64 + d] = O / l
    float i0 = 1.f / l0, i1 = 1.f / l1;
    #pragma unroll
    for (int nf = 0; nf < 8; nf++) {
        int col = qko + nf * 8 + 2 * t;
        *(float2*)(y + (size_t)r0g * CC + col) =
            make_float2(O[nf][0] * i0, O[nf][1] * i0);
        *(float2*)(y + (size_t)(r0g + 8) * CC + col) =
            make_float2(O[nf][2] * i1, O[nf][3] * i1);
    }
}

// ---------------- RMSNorm: one block per row ----------------
__global__ void rmsnorm_kernel(const float* __restrict__ x,
                               const float* __restrict__ w,
                               float* __restrict__ o, int C) {
    int row = blockIdx.x;
    const float* xr = x + (size_t)row * C;
    float s = 0.f;
    for (int i = threadIdx.x; i < C; i += blockDim.x) {
        float v = xr[i];
        s += v * v;
    }
    __shared__ float red[32];
    #pragma unroll
    for (int off = 16; off; off >>= 1) s += __shfl_down_sync(0xFFFFFFFFu, s, off);
    if ((threadIdx.x & 31) == 0) red[threadIdx.x >> 5] = s;
    __syncthreads();
    if (threadIdx.x < 32) {
        float v = (threadIdx.x < (blockDim.x >> 5)) ? red[threadIdx.x] : 0.f;
        #pragma unroll
        for (int off = 16; off; off >>= 1) v += __shfl_down_sync(0xFFFFFFFFu, v, off);
        if (threadIdx.x == 0) red[0] = v;
    }
    __syncthreads();
    float inv = rsqrtf(red[0] / (float)C + 1e-6f);
    for (int i = threadIdx.x; i < C; i += blockDim.x)
        o[(size_t)row * C + i] = xr[i] * inv * w[i];
}

// ---------------- SwiGLU elementwise ----------------
__global__ void swiglu_kernel(float4* __restrict__ h1,
                              const float4* __restrict__ h3, int n4) {
    int i = blockIdx.x * blockDim.x + threadIdx.x;
    if (i < n4) {
        float4 a = h1[i];
        float4 b = h3[i];
        a.x = a.x / (1.f + __expf(-a.x)) * b.x;
        a.y = a.y / (1.f + __expf(-a.y)) * b.y;
        a.z = a.z / (1.f + __expf(-a.z)) * b.z;
        a.w = a.w / (1.f + __expf(-a.w)) * b.w;
        h1[i] = a;
    }
}

// ---------------- launch ----------------
extern "C" void kernel_launch(void* const* d_in, const int* in_sizes, int n_in,
                              void* d_out, int out_size) {
    const float* x           = (const float*)d_in[0];
    const float* attn_norm_w = (const float*)d_in[1];
    const float* ffn_norm_w  = (const float*)d_in[2];
    const float* c_attn_w    = (const float*)d_in[3];
    const float* c_proj_w    = (const float*)d_in[4];
    const float* w1          = (const float*)d_in[5];
    const float* w2          = (const float*)d_in[6];
    const float* w3          = (const float*)d_in[7];
    float* out = (float*)d_out;

    float *xn, *qkv, *yb, *x1, *h1, *h3;
    cudaGetSymbolAddress((void**)&xn,  g_xn);
    cudaGetSymbolAddress((void**)&qkv, g_qkv);
    cudaGetSymbolAddress((void**)&yb,  g_y);
    cudaGetSymbolAddress((void**)&x1,  g_x1);
    cudaGetSymbolAddress((void**)&h1,  g_h1);
    cudaGetSymbolAddress((void**)&h3,  g_h3);

    cudaFuncSetAttribute(gemm_bf16s, cudaFuncAttributeMaxDynamicSharedMemorySize, GEMM_SMEM);
    cudaFuncSetAttribute(attn_mma, cudaFuncAttributeMaxDynamicSharedMemorySize, ATTN_SMEM);

    // 1) xn = rmsnorm(x, attn_norm_w)
    rmsnorm_kernel<<<TT, 256>>>(x, attn_norm_w, xn, CC);

    // 2) qkv = xn @ c_attn_w^T       [4096, 3072]
    gemm_bf16s<<<dim3(3 * CC / 128, TT / 128), 256, GEMM_SMEM>>>(xn, c_attn_w, qkv, TT, 3 * CC, CC, nullptr);

    // 3) y = causal_attention(qkv)   [4096, 1024]
    attn_mma<<<dim3(TT / 128, NH), 256, ATTN_SMEM>>>(qkv, yb);

    // 4) x1 = y @ c_proj_w^T + x
    gemm_bf16s<<<dim3(CC / 128, TT / 128), 256, GEMM_SMEM>>>(yb, c_proj_w, x1, TT, CC, CC, x);

    // 5) xn = rmsnorm(x1, ffn_norm_w)
    rmsnorm_kernel<<<TT, 256>>>(x1, ffn_norm_w, xn, CC);

    // 6) h1 = xn @ w1^T ; h3 = xn @ w3^T     [4096, 4096]
    gemm_bf16s<<<dim3(HF / 128, TT / 128), 256, GEMM_SMEM>>>(xn, w1, h1, TT, HF, CC, nullptr);
    gemm_bf16s<<<dim3(HF / 128, TT / 128), 256, GEMM_SMEM>>>(xn, w3, h3, TT, HF, CC, nullptr);

    // 7) h1 = silu(h1) * h3
    {
        int n4 = TT * HF / 4;
        swiglu_kernel<<<n4 / 256, 256>>>((float4*)h1, (const float4*)h3, n4);
    }

    // 8) out = h1 @ w2^T + x1
    gemm_bf16s<<<dim3(CC / 128, TT / 128), 256, GEMM_SMEM>>>(h1, w2, out, TT, CC, HF, x1);
}

// round 5
// speedup vs baseline: 3.0813x; 1.2986x over previous
#include <cuda_runtime.h>
#include <cuda_bf16.h>
#include <cstdint>
#include <math.h>

// Problem dims (fixed by the reference)
#define TT 4096
#define CC 1024
#define HF 4096
#define NH 16
#define HD 64

// ---------------- scratch (device globals: allocation-free) ----------------
__device__ float g_xn [(size_t)TT * CC];
__device__ float g_qkv[(size_t)TT * 3 * CC];
__device__ float g_y  [(size_t)TT * CC];
__device__ float g_x1 [(size_t)TT * CC];
__device__ float g_h1 [(size_t)TT * HF];
__device__ float g_h3 [(size_t)TT * HF];

// ================= helpers =================
__device__ __forceinline__ uint32_t smem_u32(const void* p) {
    uint32_t a;
    asm("{ .reg .u64 t; cvta.to.shared.u64 t, %1; cvt.u32.u64 %0, t; }" : "=r"(a) : "l"(p));
    return a;
}
// pack two floats to bf16x2: lo=a, hi=b (one instruction)
__device__ __forceinline__ uint32_t cvt2(float a, float b) {
    uint32_t r;
    asm("cvt.rn.satfinite.bf16x2.f32 %0, %1, %2;" : "=r"(r) : "f"(b), "f"(a));
    return r;
}
__device__ __forceinline__ float ex2(float x) {
    float r;
    asm("ex2.approx.f32 %0, %1;" : "=f"(r) : "f"(x));
    return r;
}
// mma.sync m16n8k16 row.col bf16 -> fp32 (family-common on sm_103)
__device__ __forceinline__ void mma_bf16(float* c, const uint32_t* a, const uint32_t* b) {
    asm volatile(
        "mma.sync.aligned.m16n8k16.row.col.f32.bf16.bf16.f32 "
        "{%0,%1,%2,%3}, {%4,%5,%6,%7}, {%8,%9}, {%0,%1,%2,%3};"
        : "+f"(c[0]), "+f"(c[1]), "+f"(c[2]), "+f"(c[3])
        : "r"(a[0]), "r"(a[1]), "r"(a[2]), "r"(a[3]), "r"(b[0]), "r"(b[1]));
}
__device__ __forceinline__ void ldsm_x4(uint32_t addr, uint32_t& b0, uint32_t& b1,
                                        uint32_t& b2, uint32_t& b3) {
    asm volatile("ldmatrix.sync.aligned.m8n8.x4.shared.b16 {%0,%1,%2,%3}, [%4];"
                 : "=r"(b0), "=r"(b1), "=r"(b2), "=r"(b3) : "r"(addr));
}
__device__ __forceinline__ void ldsm_x4_trans(uint32_t addr, uint32_t& b0, uint32_t& b1,
                                              uint32_t& b2, uint32_t& b3) {
    asm volatile("ldmatrix.sync.aligned.m8n8.x4.trans.shared.b16 {%0,%1,%2,%3}, [%4];"
                 : "=r"(b0), "=r"(b1), "=r"(b2), "=r"(b3) : "r"(addr));
}
// split float4 into bf16x2 hi pair + lo (residual) pair
__device__ __forceinline__ void split4(float4 v, uint2& h, uint2& l) {
    h.x = cvt2(v.x, v.y);
    h.y = cvt2(v.z, v.w);
    float r0 = v.x - __uint_as_float(h.x << 16);
    float r1 = v.y - __uint_as_float(h.x & 0xFFFF0000u);
    float r2 = v.z - __uint_as_float(h.y << 16);
    float r3 = v.w - __uint_as_float(h.y & 0xFFFF0000u);
    l.x = cvt2(r0, r1);
    l.y = cvt2(r2, r3);
}

// ================= bf16-split tensor-core GEMM (unchanged structure) =================
#define TROW 80
#define TILE_BYTES (128 * TROW)
#define STAGE_BYTES (4 * TILE_BYTES)
#define GEMM_SMEM (2 * STAGE_BYTES)

__global__ void __launch_bounds__(256)
gemm_bf16s(const float* __restrict__ A, const float* __restrict__ B,
           float* __restrict__ C, int M, int N, int K,
           const float* __restrict__ add) {
    extern __shared__ char smem[];

    const int tid  = threadIdx.x;
    const int warp = tid >> 5;
    const int lane = tid & 31;
    const int g = lane >> 2;
    const int t = lane & 3;
    const int wm = warp >> 2;
    const int wn = warp & 3;
    const int m0 = wm * 64;
    const int n0 = wn * 32;
    const int bm = blockIdx.y * 128;
    const int bn = blockIdx.x * 128;

    float acc[4][4][4];
    #pragma unroll
    for (int i = 0; i < 4; i++)
        #pragma unroll
        for (int j = 0; j < 4; j++)
            #pragma unroll
            for (int r = 0; r < 4; r++) acc[i][j][r] = 0.f;

    float4 va[4], vb[4];
    const int nc = K >> 5;

    {
        #pragma unroll
        for (int u = 0; u < 4; u++) {
            int s = tid + u * 256;
            int row = s >> 3, q = s & 7;
            va[u] = *(const float4*)(A + (size_t)(bm + row) * K + q * 4);
            vb[u] = *(const float4*)(B + (size_t)(bn + row) * K + q * 4);
        }
        char* base = smem;
        #pragma unroll
        for (int u = 0; u < 4; u++) {
            int s = tid + u * 256;
            int row = s >> 3, q = s & 7;
            uint32_t off = (uint32_t)row * TROW + (uint32_t)q * 8;
            uint2 h, l;
            split4(va[u], h, l);
            *(uint2*)(base + off)              = h;
            *(uint2*)(base + TILE_BYTES + off) = l;
            split4(vb[u], h, l);
            *(uint2*)(base + 2 * TILE_BYTES + off) = h;
            *(uint2*)(base + 3 * TILE_BYTES + off) = l;
        }
    }
    __syncthreads();

    for (int c = 0; c < nc; c++) {
        const int cur = c & 1;
        const bool more = (c + 1 < nc);

        if (more) {
            int k0 = (c + 1) << 5;
            #pragma unroll
            for (int u = 0; u < 4; u++) {
                int s = tid + u * 256;
                int row = s >> 3, q = s & 7;
                va[u] = *(const float4*)(A + (size_t)(bm + row) * K + k0 + q * 4);
                vb[u] = *(const float4*)(B + (size_t)(bn + row) * K + k0 + q * 4);
            }
        }

        {
            const char* base = smem + cur * STAGE_BYTES;
            const char* Ah = base;
            const char* Al = base + TILE_BYTES;
            const char* Bh = base + 2 * TILE_BYTES;
            const char* Bl = base + 3 * TILE_BYTES;

            #pragma unroll
            for (int ks = 0; ks < 2; ks++) {
                const int kb = ks * 16;
                const uint32_t kc = (uint32_t)(kb + t * 2) * 2;

                uint32_t bhf[4][2], blf[4][2];
                #pragma unroll
                for (int j = 0; j < 4; j++) {
                    uint32_t o0 = (uint32_t)(n0 + j * 8 + g) * TROW + kc;
                    bhf[j][0] = *(const uint32_t*)(Bh + o0);
                    bhf[j][1] = *(const uint32_t*)(Bh + o0 + 16);
                    blf[j][0] = *(const uint32_t*)(Bl + o0);
                    blf[j][1] = *(const uint32_t*)(Bl + o0 + 16);
                }
                #pragma unroll
                for (int i = 0; i < 4; i++) {
                    uint32_t o0 = (uint32_t)(m0 + i * 16 + g) * TROW + kc;
                    uint32_t o1 = o0 + 8 * TROW;
                    uint32_t ahf[4], alf[4];
                    ahf[0] = *(const uint32_t*)(Ah + o0);
                    ahf[1] = *(const uint32_t*)(Ah + o1);
                    ahf[2] = *(const uint32_t*)(Ah + o0 + 16);
                    ahf[3] = *(const uint32_t*)(Ah + o1 + 16);
                    alf[0] = *(const uint32_t*)(Al + o0);
                    alf[1] = *(const uint32_t*)(Al + o1);
                    alf[2] = *(const uint32_t*)(Al + o0 + 16);
                    alf[3] = *(const uint32_t*)(Al + o1 + 16);
                    #pragma unroll
                    for (int j = 0; j < 4; j++) {
                        mma_bf16(acc[i][j], ahf, bhf[j]);
                        mma_bf16(acc[i][j], ahf, blf[j]);
                        mma_bf16(acc[i][j], alf, bhf[j]);
                    }
                }
            }
        }

        if (more) {
            char* base = smem + (cur ^ 1) * STAGE_BYTES;
            #pragma unroll
            for (int u = 0; u < 4; u++) {
                int s = tid + u * 256;
                int row = s >> 3, q = s & 7;
                uint32_t off = (uint32_t)row * TROW + (uint32_t)q * 8;
                uint2 h, l;
                split4(va[u], h, l);
                *(uint2*)(base + off)              = h;
                *(uint2*)(base + TILE_BYTES + off) = l;
                split4(vb[u], h, l);
                *(uint2*)(base + 2 * TILE_BYTES + off) = h;
                *(uint2*)(base + 3 * TILE_BYTES + off) = l;
            }
        }
        __syncthreads();
    }

    #pragma unroll
    for (int i = 0; i < 4; i++) {
        size_t r0 = (size_t)(bm + m0 + i * 16 + g);
        size_t r1 = r0 + 8;
        #pragma unroll
        for (int j = 0; j < 4; j++) {
            int col = bn + n0 + j * 8 + t * 2;
            float2 v0 = make_float2(acc[i][j][0], acc[i][j][1]);
            float2 v1 = make_float2(acc[i][j][2], acc[i][j][3]);
            if (add) {
                float2 a0 = *(const float2*)(add + r0 * N + col);
                float2 a1 = *(const float2*)(add + r1 * N + col);
                v0.x += a0.x; v0.y += a0.y;
                v1.x += a1.x; v1.y += a1.y;
            }
            *(float2*)(C + r0 * N + col) = v0;
            *(float2*)(C + r1 * N + col) = v1;
        }
    }
}

// ================= MMA flash attention (causal), bf16-split, fixed-base softmax ========
// CTA: 128 q-rows x 1 head. 8 warps; warp w owns q rows [w*16, w*16+16).
// ktile = 64 keys, K/V double-buffered. P = 2^S directly (no online max: S is bounded,
// O and l scale identically so O/l is exact). l reduced once at the end.
#define ASTR 144                  // smem row stride bytes (64 bf16 + 8 pad)
#define Q_BYTES (128 * ASTR)
#define KV_BYTES (64 * ASTR)
#define BUF_BYTES (4 * KV_BYTES)  // KH, KL, VH, VL
#define ATTN_SMEM (2 * Q_BYTES + 2 * BUF_BYTES)  // 110592

__global__ void __launch_bounds__(256)
attn_mma(const float* __restrict__ qkv, float* __restrict__ y) {
    extern __shared__ char sm[];
    const uint32_t sb = smem_u32(sm);
    const int tid  = threadIdx.x;
    const int w    = tid >> 5;
    const int lane = tid & 31;
    const int g = lane >> 2, t = lane & 3;
    const int qt = 31 - (int)blockIdx.x;     // reversed: longest tiles first
    const int h  = blockIdx.y;
    const int q0 = qt * 128;
    const int C3 = 3 * CC;
    const int qko = h * HD;
    const uint32_t QH = 0, QL = Q_BYTES;
    const uint32_t BUF0 = 2 * Q_BYTES;

    // ---- load Q tile (scaled by log2e/8 BEFORE split), hi/lo STS
    const float qs = 1.4426950408889634f * 0.125f;
    #pragma unroll
    for (int u = 0; u < 8; u++) {
        int idx = tid + u * 256;
        int row = idx >> 4, dg = idx & 15;
        float4 v = *(const float4*)(qkv + (size_t)(q0 + row) * C3 + qko + dg * 4);
        v.x *= qs; v.y *= qs; v.z *= qs; v.w *= qs;
        uint32_t off = (uint32_t)row * ASTR + (uint32_t)dg * 8;
        uint2 hh, ll;
        split4(v, hh, ll);
        *(uint2*)(sm + QH + off) = hh;
        *(uint2*)(sm + QL + off) = ll;
    }
    __syncthreads();

    // ---- persistent Q A-fragments (per warp, all 4 k-steps, hi+lo)
    uint32_t qh[4][4], ql[4][4];
    {
        uint32_t rb = (uint32_t)(w * 16 + g) * ASTR + (uint32_t)t * 4;
        #pragma unroll
        for (int ks = 0; ks < 4; ks++) {
            uint32_t o = rb + ks * 32;
            qh[ks][0] = *(const uint32_t*)(sm + QH + o);
            qh[ks][1] = *(const uint32_t*)(sm + QH + o + 8 * ASTR);
            qh[ks][2] = *(const uint32_t*)(sm + QH + o + 16);
            qh[ks][3] = *(const uint32_t*)(sm + QH + o + 8 * ASTR + 16);
            ql[ks][0] = *(const uint32_t*)(sm + QL + o);
            ql[ks][1] = *(const uint32_t*)(sm + QL + o + 8 * ASTR);
            ql[ks][2] = *(const uint32_t*)(sm + QL + o + 16);
            ql[ks][3] = *(const uint32_t*)(sm + QL + o + 8 * ASTR + 16);
        }
    }

    // ---- prologue: load K/V tile 0 into buffer 0
    {
        #pragma unroll
        for (int u = 0; u < 4; u++) {
            int idx = tid + u * 256;
            int row = idx >> 4, dg = idx & 15;
            float4 kvv = *(const float4*)(qkv + (size_t)row * C3 + CC + qko + dg * 4);
            float4 vvv = *(const float4*)(qkv + (size_t)row * C3 + 2 * CC + qko + dg * 4);
            uint32_t off = BUF0 + (uint32_t)row * ASTR + (uint32_t)dg * 8;
            uint2 hh, ll;
            split4(kvv, hh, ll);
            *(uint2*)(sm + off)            = hh;
            *(uint2*)(sm + off + KV_BYTES) = ll;
            split4(vvv, hh, ll);
            *(uint2*)(sm + off + 2 * KV_BYTES) = hh;
            *(uint2*)(sm + off + 3 * KV_BYTES) = ll;
        }
    }
    __syncthreads();

    float O[8][4];
    #pragma unroll
    for (int nf = 0; nf < 8; nf++)
        #pragma unroll
        for (int r = 0; r < 4; r++) O[nf][r] = 0.f;
    float l0 = 0.f, l1 = 0.f;

    const int nk = 2 * qt + 2;
    const int r0g = q0 + w * 16 + g;          // this thread's first q row
    // ldmatrix lane offsets
    const int blk = lane >> 3, lr = lane & 7;
    const uint32_t ldsmV_off = (uint32_t)((blk & 1) * 8 + lr) * ASTR + (uint32_t)(blk >> 1) * 16;
    const uint32_t ldsmK_row = (uint32_t)(((lane >> 4) << 3) | lr);     // row within nfp pair
    const uint32_t ldsmK_col = (uint32_t)((blk & 1) * 16);

    for (int kt = 0; kt < nk; kt++) {
        const uint32_t kb = BUF0 + (uint32_t)(kt & 1) * BUF_BYTES;
        const bool more = (kt + 1 < nk);

        // prefetch next K/V into regs
        float4 pk[4], pv[4];
        if (more) {
            int k0n = (kt + 1) * 64;
            #pragma unroll
            for (int u = 0; u < 4; u++) {
                int idx = tid + u * 256;
                int row = idx >> 4, dg = idx & 15;
                pk[u] = *(const float4*)(qkv + (size_t)(k0n + row) * C3 + CC + qko + dg * 4);
                pv[u] = *(const float4*)(qkv + (size_t)(k0n + row) * C3 + 2 * CC + qko + dg * 4);
            }
        }

        // ---- S = Q K^T (3-term split), K fragments via ldmatrix.x4
        float S[8][4];
        #pragma unroll
        for (int nf = 0; nf < 8; nf++)
            #pragma unroll
            for (int r = 0; r < 4; r++) S[nf][r] = 0.f;

        {
            const uint32_t kh = sb + kb + ldsmK_row * ASTR + ldsmK_col;
            #pragma unroll
            for (int ks = 0; ks < 4; ks++) {
                #pragma unroll
                for (int nfp = 0; nfp < 4; nfp++) {
                    uint32_t a = kh + (uint32_t)(nfp * 16) * ASTR + (uint32_t)(ks * 32);
                    uint32_t h0, h1, h2, h3, l0r, l1r, l2r, l3r;
                    ldsm_x4(a, h0, h1, h2, h3);
                    ldsm_x4(a + KV_BYTES, l0r, l1r, l2r, l3r);
                    uint32_t bh0[2] = {h0, h1}, bh1[2] = {h2, h3};
                    uint32_t bl0[2] = {l0r, l1r}, bl1[2] = {l2r, l3r};
                    mma_bf16(S[2 * nfp],     qh[ks], bh0);
                    mma_bf16(S[2 * nfp],     ql[ks], bh0);
                    mma_bf16(S[2 * nfp],     qh[ks], bl0);
                    mma_bf16(S[2 * nfp + 1], qh[ks], bh1);
                    mma_bf16(S[2 * nfp + 1], ql[ks], bh1);
                    mma_bf16(S[2 * nfp + 1], qh[ks], bl1);
                }
            }
        }

        // ---- causal mask (only on/after the diagonal)
        if (kt >= 2 * qt) {
            int k0 = kt * 64;
            #pragma unroll
            for (int nf = 0; nf < 8; nf++) {
                int c = k0 + nf * 8 + 2 * t;
                if (c     > r0g)     S[nf][0] = -1e30f;
                if (c + 1 > r0g)     S[nf][1] = -1e30f;
                if (c     > r0g + 8) S[nf][2] = -1e30f;
                if (c + 1 > r0g + 8) S[nf][3] = -1e30f;
            }
        }

        // ---- fixed-base softmax: P = 2^S; accumulate l locally (no shuffles, no rescale)
        #pragma unroll
        for (int nf = 0; nf < 8; nf++) {
            S[nf][0] = ex2(S[nf][0]);
            S[nf][1] = ex2(S[nf][1]);
            S[nf][2] = ex2(S[nf][2]);
            S[nf][3] = ex2(S[nf][3]);
            l0 += S[nf][0] + S[nf][1];
            l1 += S[nf][2] + S[nf][3];
        }

        // ---- store prefetched K/V into the other buffer
        if (more) {
            uint32_t nb = BUF0 + (uint32_t)((kt + 1) & 1) * BUF_BYTES;
            #pragma unroll
            for (int u = 0; u < 4; u++) {
                int idx = tid + u * 256;
                int row = idx >> 4, dg = idx & 15;
                uint32_t off = nb + (uint32_t)row * ASTR + (uint32_t)dg * 8;
                uint2 hh, ll;
                split4(pk[u], hh, ll);
                *(uint2*)(sm + off)            = hh;
                *(uint2*)(sm + off + KV_BYTES) = ll;
                split4(pv[u], hh, ll);
                *(uint2*)(sm + off + 2 * KV_BYTES) = hh;
                *(uint2*)(sm + off + 3 * KV_BYTES) = ll;
            }
        }

        // ---- O += P V (3-term split); pack P per-ks just before use
        {
            const uint32_t vh = sb + kb + 2 * KV_BYTES + ldsmV_off;
            #pragma unroll
            for (int ks = 0; ks < 4; ks++) {
                float p00 = S[2 * ks][0], p01 = S[2 * ks][1];
                float p02 = S[2 * ks][2], p03 = S[2 * ks][3];
                float p10 = S[2 * ks + 1][0], p11 = S[2 * ks + 1][1];
                float p12 = S[2 * ks + 1][2], p13 = S[2 * ks + 1][3];
                uint32_t pah[4], pal[4];
                pah[0] = cvt2(p00, p01);
                pah[1] = cvt2(p02, p03);
                pah[2] = cvt2(p10, p11);
                pah[3] = cvt2(p12, p13);
                pal[0] = cvt2(p00 - __uint_as_float(pah[0] << 16),
                              p01 - __uint_as_float(pah[0] & 0xFFFF0000u));
                pal[1] = cvt2(p02 - __uint_as_float(pah[1] << 16),
                              p03 - __uint_as_float(pah[1] & 0xFFFF0000u));
                pal[2] = cvt2(p10 - __uint_as_float(pah[2] << 16),
                              p11 - __uint_as_float(pah[2] & 0xFFFF0000u));
                pal[3] = cvt2(p12 - __uint_as_float(pah[3] << 16),
                              p13 - __uint_as_float(pah[3] & 0xFFFF0000u));

                uint32_t ka = vh + (uint32_t)(ks * 16) * ASTR;
                #pragma unroll
                for (int np = 0; np < 4; np++) {
                    uint32_t a = ka + (uint32_t)np * 32;
                    uint32_t b0, b1, b2, b3;
                    ldsm_x4_trans(a, b0, b1, b2, b3);
                    uint32_t bb0[2] = {b0, b1}, bb1[2] = {b2, b3};
                    mma_bf16(O[2 * np],     pah, bb0);
                    mma_bf16(O[2 * np + 1], pah, bb1);
                    mma_bf16(O[2 * np],     pal, bb0);
                    mma_bf16(O[2 * np + 1], pal, bb1);
                    ldsm_x4_trans(a + KV_BYTES, b0, b1, b2, b3);
                    uint32_t cb0[2] = {b0, b1}, cb1[2] = {b2, b3};
                    mma_bf16(O[2 * np],     pah, cb0);
                    mma_bf16(O[2 * np + 1], pah, cb1);
                }
            }
        }
        __syncthreads();
    }

    // ---- final l reduction over the 4 t-lanes (columns), then write
    l0 += __shfl_xor_sync(0xFFFFFFFFu, l0, 1);
    l0 += __shfl_xor_sync(0xFFFFFFFFu, l0, 2);
    l1 += __shfl_xor_sync(0xFFFFFFFFu, l1, 1);
    l1 += __shfl_xor_sync(0xFFFFFFFFu, l1, 2);
    float i0 = 1.f / l0, i1 = 1.f / l1;
    #pragma unroll
    for (int nf = 0; nf < 8; nf++) {
        int col = qko + nf * 8 + 2 * t;
        *(float2*)(y + (size_t)r0g * CC + col) =
            make_float2(O[nf][0] * i0, O[nf][1] * i0);
        *(float2*)(y + (size_t)(r0g + 8) * CC + col) =
            make_float2(O[nf][2] * i1, O[nf][3] * i1);
    }
}

// ---------------- RMSNorm: one block per row ----------------
__global__ void rmsnorm_kernel(const float* __restrict__ x,
                               const float* __restrict__ w,
                               float* __restrict__ o, int C) {
    int row = blockIdx.x;
    const float* xr = x + (size_t)row * C;
    float s = 0.f;
    for (int i = threadIdx.x; i < C; i += blockDim.x) {
        float v = xr[i];
        s += v * v;
    }
    __shared__ float red[32];
    #pragma unroll
    for (int off = 16; off; off >>= 1) s += __shfl_down_sync(0xFFFFFFFFu, s, off);
    if ((threadIdx.x & 31) == 0) red[threadIdx.x >> 5] = s;
    __syncthreads();
    if (threadIdx.x < 32) {
        float v = (threadIdx.x < (blockDim.x >> 5)) ? red[threadIdx.x] : 0.f;
        #pragma unroll
        for (int off = 16; off; off >>= 1) v += __shfl_down_sync(0xFFFFFFFFu, v, off);
        if (threadIdx.x == 0) red[0] = v;
    }
    __syncthreads();
    float inv = rsqrtf(red[0] / (float)C + 1e-6f);
    for (int i = threadIdx.x; i < C; i += blockDim.x)
        o[(size_t)row * C + i] = xr[i] * inv * w[i];
}

// ---------------- SwiGLU elementwise ----------------
__global__ void swiglu_kernel(float4* __restrict__ h1,
                              const float4* __restrict__ h3, int n4) {
    int i = blockIdx.x * blockDim.x + threadIdx.x;
    if (i < n4) {
        float4 a = h1[i];
        float4 b = h3[i];
        a.x = a.x / (1.f + __expf(-a.x)) * b.x;
        a.y = a.y / (1.f + __expf(-a.y)) * b.y;
        a.z = a.z / (1.f + __expf(-a.z)) * b.z;
        a.w = a.w / (1.f + __expf(-a.w)) * b.w;
        h1[i] = a;
    }
}

// ---------------- launch ----------------
extern "C" void kernel_launch(void* const* d_in, const int* in_sizes, int n_in,
                              void* d_out, int out_size) {
    const float* x           = (const float*)d_in[0];
    const float* attn_norm_w = (const float*)d_in[1];
    const float* ffn_norm_w  = (const float*)d_in[2];
    const float* c_attn_w    = (const float*)d_in[3];
    const float* c_proj_w    = (const float*)d_in[4];
    const float* w1          = (const float*)d_in[5];
    const float* w2          = (const float*)d_in[6];
    const float* w3          = (const float*)d_in[7];
    float* out = (float*)d_out;

    float *xn, *qkv, *yb, *x1, *h1, *h3;
    cudaGetSymbolAddress((void**)&xn,  g_xn);
    cudaGetSymbolAddress((void**)&qkv, g_qkv);
    cudaGetSymbolAddress((void**)&yb,  g_y);
    cudaGetSymbolAddress((void**)&x1,  g_x1);
    cudaGetSymbolAddress((void**)&h1,  g_h1);
    cudaGetSymbolAddress((void**)&h3,  g_h3);

    cudaFuncSetAttribute(gemm_bf16s, cudaFuncAttributeMaxDynamicSharedMemorySize, GEMM_SMEM);
    cudaFuncSetAttribute(attn_mma, cudaFuncAttributeMaxDynamicSharedMemorySize, ATTN_SMEM);

    // 1) xn = rmsnorm(x, attn_norm_w)
    rmsnorm_kernel<<<TT, 256>>>(x, attn_norm_w, xn, CC);

    // 2) qkv = xn @ c_attn_w^T       [4096, 3072]
    gemm_bf16s<<<dim3(3 * CC / 128, TT / 128), 256, GEMM_SMEM>>>(xn, c_attn_w, qkv, TT, 3 * CC, CC, nullptr);

    // 3) y = causal_attention(qkv)   [4096, 1024]
    attn_mma<<<dim3(TT / 128, NH), 256, ATTN_SMEM>>>(qkv, yb);

    // 4) x1 = y @ c_proj_w^T + x
    gemm_bf16s<<<dim3(CC / 128, TT / 128), 256, GEMM_SMEM>>>(yb, c_proj_w, x1, TT, CC, CC, x);

    // 5) xn = rmsnorm(x1, ffn_norm_w)
    rmsnorm_kernel<<<TT, 256>>>(x1, ffn_norm_w, xn, CC);

    // 6) h1 = xn @ w1^T ; h3 = xn @ w3^T     [4096, 4096]
    gemm_bf16s<<<dim3(HF / 128, TT / 128), 256, GEMM_SMEM>>>(xn, w1, h1, TT, HF, CC, nullptr);
    gemm_bf16s<<<dim3(HF / 128, TT / 128), 256, GEMM_SMEM>>>(xn, w3, h3, TT, HF, CC, nullptr);

    // 7) h1 = silu(h1) * h3
    {
        int n4 = TT * HF / 4;
        swiglu_kernel<<<n4 / 256, 256>>>((float4*)h1, (const float4*)h3, n4);
    }

    // 8) out = h1 @ w2^T + x1
    gemm_bf16s<<<dim3(CC / 128, TT / 128), 256, GEMM_SMEM>>>(h1, w2, out, TT, CC, HF, x1);
}